// round 1
// baseline (speedup 1.0000x reference)
#include <cuda_runtime.h>
#include <math_constants.h>

// Problem constants (fixed by the reference setup_inputs)
#define BB     32
#define NN     4096
#define FDIM   128
#define LL     50
#define DHH    4
#define LDH    (LL * DHH)   // 200 floats per agent in hist_feat
#define KK     8

// Scratch: per-agent scores (j = 1..N-1 mapped to 0..N-2)
__device__ float g_scores[BB * (NN - 1)];

// ---------------------------------------------------------------------------
// Kernel 1: one warp per "other" agent. Computes the combined score.
// ---------------------------------------------------------------------------
__global__ __launch_bounds__(256)
void score_kernel(const float* __restrict__ x,     // (B, N, FDIM)
                  const float* __restrict__ hf,    // (B, N, L, DH)
                  const float* __restrict__ he,    // (B, N, FDIM)
                  float* __restrict__ scores)      // (B, N-1)
{
    const int gwarp = (blockIdx.x * blockDim.x + threadIdx.x) >> 5;
    const int lane  = threadIdx.x & 31;
    const int total = BB * (NN - 1);
    if (gwarp >= total) return;

    const int b = gwarp / (NN - 1);
    const int j = gwarp - b * (NN - 1) + 1;   // 1 .. N-1

    const float4* __restrict__ xj = (const float4*)(x  + ((size_t)b * NN + j) * FDIM);
    const float4* __restrict__ x0 = (const float4*)(x  +  (size_t)b * NN      * FDIM);
    const float4* __restrict__ ej = (const float4*)(he + ((size_t)b * NN + j) * FDIM);
    const float4* __restrict__ e0 = (const float4*)(he +  (size_t)b * NN      * FDIM);

    // 32 lanes x float4 = 128 floats
    float4 a = xj[lane];
    float4 c = x0[lane];
    float dx = a.x - c.x, dy = a.y - c.y, dz = a.z - c.z, dw = a.w - c.w;
    float d2 = dx*dx + dy*dy + dz*dz + dw*dw;

    float4 u = ej[lane];
    float4 v = e0[lane];
    float tn = u.x*v.x + u.y*v.y + u.z*v.z + u.w*v.w;
    float uu = u.x*u.x + u.y*u.y + u.z*u.z + u.w*u.w;
    float vv = v.x*v.x + v.y*v.y + v.z*v.z + v.w*v.w;

    #pragma unroll
    for (int off = 16; off > 0; off >>= 1) {
        d2 += __shfl_xor_sync(0xffffffffu, d2, off);
        tn += __shfl_xor_sync(0xffffffffu, tn, off);
        uu += __shfl_xor_sync(0xffffffffu, uu, off);
        vv += __shfl_xor_sync(0xffffffffu, vv, off);
    }

    if (lane == 0) {
        // --- velocity direction: hist_feat[b, agent, 48..49, 0..1] ---
        const float* hj = hf + ((size_t)b * NN + j) * LDH;
        const float* h0 = hf +  (size_t)b * NN      * LDH;
        float2 pj48 = *(const float2*)(hj + 48 * DHH);   // floats 192,193
        float2 pj49 = *(const float2*)(hj + 49 * DHH);   // floats 196,197
        float2 p048 = *(const float2*)(h0 + 48 * DHH);
        float2 p049 = *(const float2*)(h0 + 49 * DHH);

        float djx = pj49.x - pj48.x, djy = pj49.y - pj48.y;
        float d0x = p049.x - p048.x, d0y = p049.y - p048.y;

        float n0 = sqrtf(d0x*d0x + d0y*d0y);
        float inv0 = 1.0f / fmaxf(n0, 1e-12f);
        float cdx = d0x * inv0 + 1e-8f;
        float cdy = d0y * inv0 + 1e-8f;

        float nj = sqrtf(djx*djx + djy*djy);
        float invj = 1.0f / fmaxf(nj, 1e-12f);
        float odx = djx * invj + 1e-8f;
        float ody = djy * invj + 1e-8f;

        float vnum = odx*cdx + ody*cdy;
        float vden = fmaxf(sqrtf(odx*odx + ody*ody), 1e-8f) *
                     fmaxf(sqrtf(cdx*cdx + cdy*cdy), 1e-8f);
        float vsim = vnum / vden;

        // --- trajectory cosine ---
        float tsim = tn / (fmaxf(sqrtf(uu), 1e-8f) * fmaxf(sqrtf(vv), 1e-8f));

        float dist = sqrtf(d2);
        float score = 0.3f * dist
                    + 0.5f * (1.0f - fmaxf(vsim, 0.0f))
                    + 0.4f * (1.0f - fmaxf(tsim, 0.0f));
        scores[b * (NN - 1) + (j - 1)] = score;
    }
}

// ---------------------------------------------------------------------------
// Kernel 2: one block per batch. 8x argmin over 4095 scores (tie -> smaller
// index, matching lax.top_k), then gather rows + write indices.
// Output layout: [B*K*FDIM floats closest_agents][B*K floats indices]
// ---------------------------------------------------------------------------
__global__ __launch_bounds__(1024)
void topk_gather_kernel(const float* __restrict__ scores,
                        const float* __restrict__ x,
                        float* __restrict__ out)
{
    const int b = blockIdx.x;
    const int t = threadIdx.x;

    __shared__ float s[NN];          // 16 KB
    __shared__ float rv[1024];
    __shared__ int   ri[1024];
    __shared__ int   sel[KK];

    const float* sb = scores + (size_t)b * (NN - 1);
    for (int i = t; i < NN - 1; i += 1024) s[i] = sb[i];
    if (t == 0) s[NN - 1] = CUDART_INF_F;   // pad
    __syncthreads();

    for (int iter = 0; iter < KK; iter++) {
        float bv = CUDART_INF_F;
        int   bi = NN - 1;
        #pragma unroll
        for (int i = t; i < NN; i += 1024) {
            float vvl = s[i];
            if (vvl < bv) { bv = vvl; bi = i; }   // strict < keeps smaller idx
        }
        rv[t] = bv; ri[t] = bi;
        __syncthreads();
        #pragma unroll
        for (int off = 512; off > 0; off >>= 1) {
            if (t < off) {
                float v2 = rv[t + off]; int i2 = ri[t + off];
                if (v2 < rv[t] || (v2 == rv[t] && i2 < ri[t])) {
                    rv[t] = v2; ri[t] = i2;
                }
            }
            __syncthreads();
        }
        if (t == 0) { sel[iter] = ri[0]; s[ri[0]] = CUDART_INF_F; }
        __syncthreads();
    }

    // Gather: closest_agents[b, kk, :] = x[b, 1 + sel[kk], :]
    if (t < KK * FDIM) {
        int kk = t >> 7;          // /128
        int f  = t & (FDIM - 1);
        int idx = sel[kk];
        out[((size_t)b * KK + kk) * FDIM + f] =
            x[((size_t)b * NN + idx + 1) * FDIM + f];
    }
    // Indices (as float32 numeric values), appended after closest_agents
    if (t < KK) {
        out[(size_t)BB * KK * FDIM + b * KK + t] = (float)sel[t];
    }
}

extern "C" void kernel_launch(void* const* d_in, const int* in_sizes, int n_in,
                              void* d_out, int out_size)
{
    const float* x  = (const float*)d_in[0];   // (B, N, FDIM) f32
    const float* hf = (const float*)d_in[1];   // (B, N, L, DH) f32
    const float* he = (const float*)d_in[2];   // (B, N, FDIM) f32
    // d_in[3] is k == 8 (compile-time constant here)
    float* out = (float*)d_out;

    float* scores;
    cudaGetSymbolAddress((void**)&scores, g_scores);

    const int total_warps = BB * (NN - 1);
    const int threads = 256;
    const int warps_per_block = threads / 32;
    const int blocks = (total_warps + warps_per_block - 1) / warps_per_block;

    score_kernel<<<blocks, threads>>>(x, hf, he, scores);
    topk_gather_kernel<<<BB, 1024>>>(scores, x, out);
}

// round 2
// speedup vs baseline: 1.3343x; 1.3343x over previous
#include <cuda_runtime.h>

// Problem constants (fixed by the reference setup_inputs)
#define BB     32
#define NN     4096
#define FDIM   128
#define LDH    200          // L*DH floats per agent in hist_feat
#define KK     8
#define APW    32           // agents per warp
#define WPB    8            // warps per block
#define APB    (APW * WPB)  // 256 agents per block
#define CHUNKS 16           // ceil(4095 / 256)
#define CANDS  (CHUNKS * KK)  // 128 candidate keys per batch

#define KEY_MAX 0xFFFFFFFFFFFFFFFFull

__device__ unsigned long long g_cand[BB * CANDS];

static __device__ __forceinline__ unsigned long long umin64(unsigned long long a,
                                                            unsigned long long b) {
    return a < b ? a : b;
}

// ---------------------------------------------------------------------------
// Kernel 1: score + hierarchical top-8.
// One warp handles 32 consecutive agents; block covers 256 agents of a batch.
// Keys: (score_bits << 32) | (j-1)  -> min-order = (score asc, index asc),
// exactly matching lax.top_k(-score) tie-break semantics.
// ---------------------------------------------------------------------------
__global__ __launch_bounds__(256)
void score_topk_kernel(const float* __restrict__ x,   // (B, N, FDIM)
                       const float* __restrict__ hf,  // (B, N, L, DH)
                       const float* __restrict__ he,  // (B, N, FDIM)
                       unsigned long long* __restrict__ cand)
{
    const int b     = blockIdx.x / CHUNKS;
    const int chunk = blockIdx.x % CHUNKS;
    const int warp  = threadIdx.x >> 5;
    const int lane  = threadIdx.x & 31;
    const int j0    = 1 + chunk * APB + warp * APW;   // first agent of this warp

    // ---- center rows (loaded once per warp, live in registers) ----
    const float4* __restrict__ x0 = (const float4*)(x  + (size_t)b * NN * FDIM);
    const float4* __restrict__ e0 = (const float4*)(he + (size_t)b * NN * FDIM);
    float4 c = x0[lane];
    float4 v = e0[lane];

    // center-embedding norm, reduced once (butterfly -> all lanes)
    float vv = v.x*v.x + v.y*v.y + v.z*v.z + v.w*v.w;
    #pragma unroll
    for (int off = 16; off > 0; off >>= 1)
        vv += __shfl_xor_sync(0xffffffffu, vv, off);
    const float vnm = fmaxf(sqrtf(vv), 1e-8f);

    // ---- center direction (cheap, all lanes compute identically) ----
    const float* h0 = hf + (size_t)b * NN * LDH;
    float2 p048 = *(const float2*)(h0 + 192);
    float2 p049 = *(const float2*)(h0 + 196);
    float d0x = p049.x - p048.x, d0y = p049.y - p048.y;
    float inv0 = 1.0f / fmaxf(sqrtf(d0x*d0x + d0y*d0y), 1e-12f);
    float cdx = d0x * inv0 + 1e-8f;
    float cdy = d0y * inv0 + 1e-8f;
    const float cnorm = fmaxf(sqrtf(cdx*cdx + cdy*cdy), 1e-8f);

    // ---- per-lane velocity similarity: lane l handles agent j0+l ----
    // (32 scattered hist_feat sectors issued in parallel instead of 32
    //  serial lane-0 loads)
    float vsim = 0.0f;
    {
        int jl = j0 + lane;
        if (jl < NN) {
            const float* hj = hf + ((size_t)b * NN + jl) * LDH;
            float2 a48 = *(const float2*)(hj + 192);
            float2 a49 = *(const float2*)(hj + 196);
            float djx = a49.x - a48.x, djy = a49.y - a48.y;
            float invj = 1.0f / fmaxf(sqrtf(djx*djx + djy*djy), 1e-12f);
            float odx = djx * invj + 1e-8f;
            float ody = djy * invj + 1e-8f;
            float vnum = odx*cdx + ody*cdy;
            float vden = fmaxf(sqrtf(odx*odx + ody*ody), 1e-8f) * cnorm;
            vsim = vnum / vden;
        }
    }

    // ---- main loop: 3 shuffle-reduced dots per agent ----
    unsigned long long mykey = KEY_MAX;   // lane l will hold key of agent j0+l

    #pragma unroll 4
    for (int i = 0; i < APW; i++) {
        int j = j0 + i;
        if (j < NN) {
            float4 a = ((const float4*)(x  + ((size_t)b * NN + j) * FDIM))[lane];
            float4 u = ((const float4*)(he + ((size_t)b * NN + j) * FDIM))[lane];

            float dx = a.x - c.x, dy = a.y - c.y, dz = a.z - c.z, dw = a.w - c.w;
            float d2 = dx*dx + dy*dy + dz*dz + dw*dw;
            float tn = u.x*v.x + u.y*v.y + u.z*v.z + u.w*v.w;
            float uu = u.x*u.x + u.y*u.y + u.z*u.z + u.w*u.w;

            #pragma unroll
            for (int off = 16; off > 0; off >>= 1) {
                d2 += __shfl_xor_sync(0xffffffffu, d2, off);
                tn += __shfl_xor_sync(0xffffffffu, tn, off);
                uu += __shfl_xor_sync(0xffffffffu, uu, off);
            }

            float vs   = __shfl_sync(0xffffffffu, vsim, i);
            float tsim = tn / (fmaxf(sqrtf(uu), 1e-8f) * vnm);
            float score = 0.3f * sqrtf(d2)
                        + 0.5f * (1.0f - fmaxf(vs,   0.0f))
                        + 0.4f * (1.0f - fmaxf(tsim, 0.0f));
            score = fmaxf(score, 0.0f);   // keep bit-pattern order-preserving

            if (lane == i)
                mykey = ((unsigned long long)__float_as_uint(score) << 32)
                      | (unsigned int)(j - 1);
        }
    }

    // ---- warp top-8: 8 rounds of 64-bit butterfly argmin ----
    __shared__ unsigned long long skeys[WPB * KK];
    unsigned long long sel = KEY_MAX;
    #pragma unroll
    for (int it = 0; it < KK; it++) {
        unsigned long long m = mykey;
        #pragma unroll
        for (int off = 16; off > 0; off >>= 1)
            m = umin64(m, __shfl_xor_sync(0xffffffffu, m, off));
        if (mykey == m) mykey = KEY_MAX;      // keys unique -> single winner
        if (lane == it) sel = m;
    }
    if (lane < KK) skeys[warp * KK + lane] = sel;
    __syncthreads();

    // ---- block merge: warp 0 reduces 64 -> 8 ----
    if (warp == 0) {
        unsigned long long k0 = skeys[lane];
        unsigned long long k1 = skeys[lane + 32];
        unsigned long long sel2 = KEY_MAX;
        #pragma unroll
        for (int it = 0; it < KK; it++) {
            unsigned long long m = umin64(k0, k1);
            #pragma unroll
            for (int off = 16; off > 0; off >>= 1)
                m = umin64(m, __shfl_xor_sync(0xffffffffu, m, off));
            if (k0 == m) k0 = KEY_MAX;
            else if (k1 == m) k1 = KEY_MAX;
            if (lane == it) sel2 = m;
        }
        if (lane < KK)
            cand[((size_t)b * CHUNKS + chunk) * KK + lane] = sel2;
    }
}

// ---------------------------------------------------------------------------
// Kernel 2: per batch, reduce 128 candidates -> final top-8, gather rows.
// Output layout: [B*K*FDIM floats closest_agents][B*K floats indices]
// ---------------------------------------------------------------------------
__global__ __launch_bounds__(256)
void final_topk_gather(const unsigned long long* __restrict__ cand,
                       const float* __restrict__ x,
                       float* __restrict__ out)
{
    const int b = blockIdx.x;
    const int t = threadIdx.x;
    __shared__ int sel_idx[KK];

    if (t < 32) {
        const int lane = t;
        unsigned long long k[4];
        #pragma unroll
        for (int q = 0; q < 4; q++)
            k[q] = cand[(size_t)b * CANDS + q * 32 + lane];

        #pragma unroll
        for (int it = 0; it < KK; it++) {
            unsigned long long m = umin64(umin64(k[0], k[1]), umin64(k[2], k[3]));
            #pragma unroll
            for (int off = 16; off > 0; off >>= 1)
                m = umin64(m, __shfl_xor_sync(0xffffffffu, m, off));
            #pragma unroll
            for (int q = 0; q < 4; q++)
                if (k[q] == m) k[q] = KEY_MAX;
            if (lane == 0) sel_idx[it] = (int)(unsigned int)(m & 0xFFFFFFFFu);
        }
    }
    __syncthreads();

    // gather: 256 threads = 8 rows x 32 lanes of float4
    const int kk = t >> 5;
    const int l  = t & 31;
    const int idx = sel_idx[kk];
    float4 val = ((const float4*)(x + ((size_t)b * NN + idx + 1) * FDIM))[l];
    ((float4*)(out + ((size_t)b * KK + kk) * FDIM))[l] = val;

    if (t < KK)
        out[(size_t)BB * KK * FDIM + b * KK + t] = (float)sel_idx[t];
}

extern "C" void kernel_launch(void* const* d_in, const int* in_sizes, int n_in,
                              void* d_out, int out_size)
{
    const float* x  = (const float*)d_in[0];   // (B, N, FDIM) f32
    const float* hf = (const float*)d_in[1];   // (B, N, L, DH) f32
    const float* he = (const float*)d_in[2];   // (B, N, FDIM) f32
    float* out = (float*)d_out;

    unsigned long long* cand;
    cudaGetSymbolAddress((void**)&cand, g_cand);

    score_topk_kernel<<<BB * CHUNKS, 256>>>(x, hf, he, cand);
    final_topk_gather<<<BB, 256>>>(cand, x, out);
}